// round 4
// baseline (speedup 1.0000x reference)
#include <cuda_runtime.h>
#include <cuda_fp16.h>
#include <cstdint>

#define NPTS 100000
#define BSZ  8
#define CIMG 512
#define CPT  256
#define IMH  48
#define IMW  160
#define HW   (IMH*IMW)      /* 7680  */
#define NPIX (BSZ*HW)       /* 61440 */

// Scratch (device globals; no allocation in kernel_launch)
__device__ __half g_Wh[CPT * CIMG];                  // align_w in fp16, row-major (256,512)
__device__ __half g_pix[(size_t)NPIX * CPT];         // channel-last projected pixels, fp16

// ---------------------------------------------------------------------------
// Kernel 0: convert align_w (f32) -> fp16
// ---------------------------------------------------------------------------
__global__ void convW_kernel(const float* __restrict__ W) {
    int i = blockIdx.x * blockDim.x + threadIdx.x;
    if (i < CPT * CIMG) g_Wh[i] = __float2half_rn(W[i]);
}

// ---------------------------------------------------------------------------
// Kernel 1: per-batch GEMM  pix_b(7680x256) = G_b^T(7680x512) @ W^T(512x256)
//   fp16 mma.sync m16n8k16, fp32 accumulate, fp16 output to g_pix.
//   Block tile BM=128 x BN=128, BK=32, 8 warps (2m x 4n), warp tile 64x32.
//   64 accum regs/thread -> 2 CTAs/SM; latency hidden by TLP (16 warps/SM).
// ---------------------------------------------------------------------------
#define BM 128
#define BN 128
#define BK 32

__global__ __launch_bounds__(256, 2)
void gemm_pix_kernel(const float* __restrict__ img) {
    __shared__ __half As[BK][BM + 8];   // [k][m], pad -> conflict-free ldmatrix.trans
    __shared__ __half Bs[BN][BK + 8];   // [n][k], pad -> conflict-free ldmatrix

    const int b  = blockIdx.z;
    const int p0 = blockIdx.x * BM;
    const int n0 = blockIdx.y * BN;
    const float* gA = img + (size_t)b * CIMG * HW;

    const int tid  = threadIdx.x;
    const int lane = tid & 31;
    const int warp = tid >> 5;
    const int wm   = warp & 1;    // m offset wm*64
    const int wn   = warp >> 1;   // n offset wn*32

    float acc[4][4][4];
    #pragma unroll
    for (int i = 0; i < 4; i++)
        #pragma unroll
        for (int j = 0; j < 4; j++)
            #pragma unroll
            for (int k = 0; k < 4; k++) acc[i][j][k] = 0.f;

    for (int kt = 0; kt < CIMG; kt += BK) {
        // A tile: 32 k-rows x 128 pixels (f32 -> fp16), float4 per access
        #pragma unroll
        for (int i = 0; i < 4; i++) {
            int idx = tid + i * 256;          // 0..1023
            int kk  = idx >> 5;               // 0..31
            int m4  = (idx & 31) << 2;        // 0..124 step 4
            float4 v = *reinterpret_cast<const float4*>(gA + (size_t)(kt + kk) * HW + p0 + m4);
            *reinterpret_cast<__half2*>(&As[kk][m4])     = __floats2half2_rn(v.x, v.y);
            *reinterpret_cast<__half2*>(&As[kk][m4 + 2]) = __floats2half2_rn(v.z, v.w);
        }
        // B tile: 128 n-rows x 32 k (fp16), uint4 per access
        #pragma unroll
        for (int i = 0; i < 2; i++) {
            int idx = tid + i * 256;          // 0..511
            int n   = idx >> 2;               // 0..127
            int k8  = (idx & 3) << 3;         // 0,8,16,24
            uint4 v = *reinterpret_cast<const uint4*>(&g_Wh[(n0 + n) * CIMG + kt + k8]);
            *reinterpret_cast<uint4*>(&Bs[n][k8]) = v;
        }
        __syncthreads();

        #pragma unroll
        for (int ks = 0; ks < BK; ks += 16) {
            uint32_t af[4][4];
            uint32_t bfr[4][2];
            {
                int jj = lane >> 3, r = lane & 7;
                int m_off = (jj & 1) * 8, k_off = (jj >> 1) * 8;
                #pragma unroll
                for (int mt = 0; mt < 4; mt++) {
                    uint32_t addr = (uint32_t)__cvta_generic_to_shared(
                        &As[ks + k_off + r][wm * 64 + mt * 16 + m_off]);
                    asm volatile("ldmatrix.sync.aligned.m8n8.x4.trans.shared.b16 {%0,%1,%2,%3}, [%4];"
                                 : "=r"(af[mt][0]), "=r"(af[mt][1]), "=r"(af[mt][2]), "=r"(af[mt][3])
                                 : "r"(addr));
                }
                int jb = (lane >> 3) & 1;
                #pragma unroll
                for (int nt = 0; nt < 4; nt++) {
                    uint32_t addr = (uint32_t)__cvta_generic_to_shared(
                        &Bs[wn * 32 + nt * 8 + r][ks + jb * 8]);
                    asm volatile("ldmatrix.sync.aligned.m8n8.x2.shared.b16 {%0,%1}, [%2];"
                                 : "=r"(bfr[nt][0]), "=r"(bfr[nt][1])
                                 : "r"(addr));
                }
            }
            #pragma unroll
            for (int mt = 0; mt < 4; mt++)
                #pragma unroll
                for (int nt = 0; nt < 4; nt++) {
                    asm volatile("mma.sync.aligned.m16n8k16.row.col.f32.f16.f16.f32 "
                                 "{%0,%1,%2,%3}, {%4,%5,%6,%7}, {%8,%9}, {%0,%1,%2,%3};"
                                 : "+f"(acc[mt][nt][0]), "+f"(acc[mt][nt][1]),
                                   "+f"(acc[mt][nt][2]), "+f"(acc[mt][nt][3])
                                 : "r"(af[mt][0]), "r"(af[mt][1]), "r"(af[mt][2]), "r"(af[mt][3]),
                                   "r"(bfr[nt][0]), "r"(bfr[nt][1]));
                }
        }
        __syncthreads();
    }

    // Epilogue: write fp16 channel-last pix
    const int mrow = lane >> 2;
    const int ncol = (lane & 3) * 2;
    #pragma unroll
    for (int mt = 0; mt < 4; mt++) {
        #pragma unroll
        for (int nt = 0; nt < 4; nt++) {
            int m = wm * 64 + mt * 16 + mrow;
            int n = n0 + wn * 32 + nt * 8 + ncol;
            size_t base = ((size_t)(b * HW + p0 + m)) * CPT + n;
            *reinterpret_cast<__half2*>(&g_pix[base]) =
                __floats2half2_rn(acc[mt][nt][0], acc[mt][nt][1]);
            *reinterpret_cast<__half2*>(&g_pix[base + 8 * CPT]) =
                __floats2half2_rn(acc[mt][nt][2], acc[mt][nt][3]);
        }
    }
}

// ---------------------------------------------------------------------------
// Kernel 2: per-point projection + bilinear combine of precomputed pix + bias
//   One warp per point, 8 channels per lane: corner reads are 1 uint4 (16B)
//   each, pf/out are 2x float4. Single channel iteration (halved LSU count).
// ---------------------------------------------------------------------------
__global__ void fuse_kernel(const float* __restrict__ pf,
                            const float* __restrict__ centers,
                            const float* __restrict__ P2,
                            const float* __restrict__ R0,
                            const float* __restrict__ Tr,
                            const float* __restrict__ bias,
                            const int*   __restrict__ bidx,
                            float* __restrict__ out) {
    const int gw   = (blockIdx.x * blockDim.x + threadIdx.x) >> 5;
    const int lane = threadIdx.x & 31;
    if (gw >= NPTS) return;
    const int n = gw;
    const int b = bidx[n];

    const float px = centers[n * 3 + 0];
    const float py = centers[n * 3 + 1];
    const float pz = centers[n * 3 + 2];
    const float* tr = Tr + b * 16;
    const float* r0 = R0 + b * 16;
    const float* p2 = P2 + b * 12;

    float cam[4], rect[4], im[3];
    #pragma unroll
    for (int i = 0; i < 4; i++)
        cam[i] = tr[i*4+0]*px + tr[i*4+1]*py + tr[i*4+2]*pz + tr[i*4+3];
    #pragma unroll
    for (int i = 0; i < 4; i++)
        rect[i] = r0[i*4+0]*cam[0] + r0[i*4+1]*cam[1] + r0[i*4+2]*cam[2] + r0[i*4+3]*cam[3];
    #pragma unroll
    for (int i = 0; i < 3; i++)
        im[i] = p2[i*4+0]*rect[0] + p2[i*4+1]*rect[1] + p2[i*4+2]*rect[2] + p2[i*4+3]*rect[3];

    const float zc    = im[2];
    const float depth = fmaxf(zc, 1e-5f);
    const float u     = im[0] / depth;
    const float v     = im[1] / depth;
    const bool valid  = (zc > 0.f) && (u >= 0.f) && (u < (float)IMW) && (v >= 0.f) && (v < (float)IMH);

    const float x0f = floorf(u), y0f = floorf(v);
    const float wx1 = u - x0f, wx0 = 1.f - wx1;
    const float wy1 = v - y0f, wy0 = 1.f - wy1;
    const int xi0 = (int)x0f, yi0 = (int)y0f;

    const float cw[4] = {wx0 * wy0, wx1 * wy0, wx0 * wy1, wx1 * wy1};
    float wgt[4];
    const __half* rp[4];
    #pragma unroll
    for (int k = 0; k < 4; k++) {
        int xi = xi0 + (k & 1);
        int yi = yi0 + (k >> 1);
        bool inb = (xi >= 0) && (xi <= IMW - 1) && (yi >= 0) && (yi <= IMH - 1);
        wgt[k] = (valid && inb) ? cw[k] : 0.f;
        int xc = min(max(xi, 0), IMW - 1);
        int yc = min(max(yi, 0), IMH - 1);
        rp[k] = &g_pix[((size_t)((b * IMH + yc) * IMW + xc)) * CPT];
    }

    const int c = lane * 8;                 // 8 channels per lane, 32*8 = 256
    float a[8];
    #pragma unroll
    for (int j = 0; j < 8; j++) a[j] = 0.f;

    #pragma unroll
    for (int k = 0; k < 4; k++) {
        if (wgt[k] != 0.f) {
            uint4 raw = *reinterpret_cast<const uint4*>(rp[k] + c);
            const __half2* h = reinterpret_cast<const __half2*>(&raw);
            #pragma unroll
            for (int j = 0; j < 4; j++) {
                float2 f = __half22float2(h[j]);
                a[2*j]   = fmaf(wgt[k], f.x, a[2*j]);
                a[2*j+1] = fmaf(wgt[k], f.y, a[2*j+1]);
            }
        }
    }

    const float* pfrow = pf + (size_t)n * CPT + c;
    float*       orow  = out + (size_t)n * CPT + c;
    #pragma unroll
    for (int h = 0; h < 2; h++) {
        float4 pfv = *reinterpret_cast<const float4*>(pfrow + h * 4);
        float4 bv  = *reinterpret_cast<const float4*>(bias + c + h * 4);
        float4 o;
        o.x = pfv.x + (a[4*h+0] + bv.x);
        o.y = pfv.y + (a[4*h+1] + bv.y);
        o.z = pfv.z + (a[4*h+2] + bv.z);
        o.w = pfv.w + (a[4*h+3] + bv.w);
        *reinterpret_cast<float4*>(orow + h * 4) = o;
    }
}

// ---------------------------------------------------------------------------
// Launch
// ---------------------------------------------------------------------------
extern "C" void kernel_launch(void* const* d_in, const int* in_sizes, int n_in,
                              void* d_out, int out_size) {
    const float* point_feat = (const float*)d_in[0];
    const float* centers    = (const float*)d_in[1];
    const float* img_feat   = (const float*)d_in[2];
    const float* P2         = (const float*)d_in[3];
    const float* R0         = (const float*)d_in[4];
    const float* Tr         = (const float*)d_in[5];
    const float* align_w    = (const float*)d_in[6];
    const float* align_b    = (const float*)d_in[7];
    const int*   bidx       = (const int*)d_in[8];
    float* out = (float*)d_out;

    convW_kernel<<<(CPT * CIMG + 255) / 256, 256>>>(align_w);
    gemm_pix_kernel<<<dim3(HW / BM, CPT / BN, BSZ), 256>>>(img_feat);
    fuse_kernel<<<(NPTS + 7) / 8, 256>>>(point_feat, centers, P2, R0, Tr, align_b, bidx, out);
}

// round 5
// speedup vs baseline: 1.4505x; 1.4505x over previous
#include <cuda_runtime.h>
#include <cuda_fp16.h>
#include <cstdint>

#define NPTS 100000
#define BSZ  8
#define CIMG 512
#define CPT  256
#define IMH  48
#define IMW  160
#define HW   (IMH*IMW)      /* 7680  */
#define NPIX (BSZ*HW)       /* 61440 */

// Scratch (device globals; no allocation in kernel_launch)
__device__ __half g_Wh[CPT * CIMG];                  // align_w in fp16, row-major (256,512)
__device__ __half g_pix[(size_t)NPIX * CPT];         // channel-last projected pixels, fp16

// ---------------------------------------------------------------------------
// Kernel 0: convert align_w (f32) -> fp16
// ---------------------------------------------------------------------------
__global__ void convW_kernel(const float* __restrict__ W) {
    int i = blockIdx.x * blockDim.x + threadIdx.x;
    if (i < CPT * CIMG) g_Wh[i] = __float2half_rn(W[i]);
}

// ---------------------------------------------------------------------------
// Kernel 1: per-batch GEMM  pix_b(7680x256) = G_b^T(7680x512) @ W^T(512x256)
//   cp.async 3-stage pipeline. A staged as raw f32 (16B chunks), converted
//   on-chip to fp16 (LDS f32 -> STS fp16) before ldmatrix. B staged fp16.
//   Block tile BM=128 x BN=256 (A read exactly once), BK=32, 8 warps,
//   warp tile 64x64, fp16 mma m16n8k16 with f32 accum.
// ---------------------------------------------------------------------------
#define BM 128
#define BN 256
#define BK 32
#define STAGES 3

#define A_STAGE_BYTES (BK * BM * 4)            /* 16384 */
#define B_ROW_H       (BK + 8)                 /* 40 halves, 80B row stride */
#define B_STAGE_H     (BN * B_ROW_H)           /* 10240 halves = 20480 B */
#define AH_ROW_H      (BM + 8)                 /* 136 halves, 272B row */
#define SMEM_TOTAL (STAGES * A_STAGE_BYTES + STAGES * B_STAGE_H * 2 + BK * AH_ROW_H * 2)

__device__ __forceinline__ void cp16(void* s, const void* g) {
    uint32_t sa = (uint32_t)__cvta_generic_to_shared(s);
    asm volatile("cp.async.cg.shared.global [%0], [%1], 16;" :: "r"(sa), "l"(g));
}

__global__ __launch_bounds__(256, 1)
void gemm_pix_kernel(const float* __restrict__ img) {
    extern __shared__ char smem_raw[];
    float*  Af = reinterpret_cast<float*>(smem_raw);                       // [STAGES][BK][BM]
    __half* Bs = reinterpret_cast<__half*>(smem_raw + STAGES * A_STAGE_BYTES); // [STAGES][BN][B_ROW_H]
    __half* Ah = reinterpret_cast<__half*>(smem_raw + STAGES * A_STAGE_BYTES
                                           + STAGES * B_STAGE_H * 2);      // [BK][AH_ROW_H]

    const int b  = blockIdx.z;
    const int p0 = blockIdx.x * BM;
    const float* gA = img + (size_t)b * CIMG * HW;

    const int tid  = threadIdx.x;
    const int lane = tid & 31;
    const int warp = tid >> 5;
    const int wm   = warp & 1;    // m offset wm*64
    const int wn   = warp >> 1;   // n offset wn*64

    // Per-thread copy mapping (1024 16B chunks per operand per stage, 4/thread)
    // A: chunk idx -> k=idx>>5, m-chunk=(idx&31)  (row = 128 f32 = 32 chunks)
    // B: chunk idx -> n=idx>>2, k-chunk=idx&3     (row = 32 fp16 = 4 chunks)

    float acc[4][8][4];
    #pragma unroll
    for (int i = 0; i < 4; i++)
        #pragma unroll
        for (int j = 0; j < 8; j++)
            #pragma unroll
            for (int k = 0; k < 4; k++) acc[i][j][k] = 0.f;

    // Prologue: issue STAGES tiles
    #pragma unroll
    for (int s = 0; s < STAGES; s++) {
        const int kt = s * BK;
        #pragma unroll
        for (int i = 0; i < 4; i++) {
            int idx = tid + i * 256;
            int k  = idx >> 5, mc = (idx & 31) << 2;
            cp16(&Af[s * (BK * BM) + k * BM + mc],
                 gA + (size_t)(kt + k) * HW + p0 + mc);
            int n = idx >> 2, kc = (idx & 3) << 3;
            cp16(&Bs[s * B_STAGE_H + n * B_ROW_H + kc],
                 &g_Wh[n * CIMG + kt + kc]);
        }
        asm volatile("cp.async.commit_group;");
    }

    const int NT = CIMG / BK;   // 16
    for (int t = 0; t < NT; t++) {
        asm volatile("cp.async.wait_group %0;" :: "n"(STAGES - 1));
        __syncthreads();
        const int slot = t % STAGES;

        // Convert f32 stage -> fp16 Ah
        #pragma unroll
        for (int i = 0; i < 4; i++) {
            int idx = tid + i * 256;
            int k = idx >> 5, m4 = (idx & 31) << 2;
            float4 v = *reinterpret_cast<const float4*>(&Af[slot * (BK * BM) + k * BM + m4]);
            *reinterpret_cast<__half2*>(&Ah[k * AH_ROW_H + m4])     = __floats2half2_rn(v.x, v.y);
            *reinterpret_cast<__half2*>(&Ah[k * AH_ROW_H + m4 + 2]) = __floats2half2_rn(v.z, v.w);
        }
        __syncthreads();

        #pragma unroll
        for (int ks = 0; ks < BK; ks += 16) {
            uint32_t af[4][4];
            uint32_t bfr[8][2];
            {
                int jj = lane >> 3, r = lane & 7;
                int m_off = (jj & 1) * 8, k_off = (jj >> 1) * 8;
                #pragma unroll
                for (int mt = 0; mt < 4; mt++) {
                    uint32_t addr = (uint32_t)__cvta_generic_to_shared(
                        &Ah[(ks + k_off + r) * AH_ROW_H + wm * 64 + mt * 16 + m_off]);
                    asm volatile("ldmatrix.sync.aligned.m8n8.x4.trans.shared.b16 {%0,%1,%2,%3}, [%4];"
                                 : "=r"(af[mt][0]), "=r"(af[mt][1]), "=r"(af[mt][2]), "=r"(af[mt][3])
                                 : "r"(addr));
                }
                int jb = (lane >> 3) & 1;
                #pragma unroll
                for (int nt = 0; nt < 8; nt++) {
                    uint32_t addr = (uint32_t)__cvta_generic_to_shared(
                        &Bs[slot * B_STAGE_H + (wn * 64 + nt * 8 + r) * B_ROW_H + ks + jb * 8]);
                    asm volatile("ldmatrix.sync.aligned.m8n8.x2.shared.b16 {%0,%1}, [%2];"
                                 : "=r"(bfr[nt][0]), "=r"(bfr[nt][1])
                                 : "r"(addr));
                }
            }
            #pragma unroll
            for (int mt = 0; mt < 4; mt++)
                #pragma unroll
                for (int nt = 0; nt < 8; nt++) {
                    asm volatile("mma.sync.aligned.m16n8k16.row.col.f32.f16.f16.f32 "
                                 "{%0,%1,%2,%3}, {%4,%5,%6,%7}, {%8,%9}, {%0,%1,%2,%3};"
                                 : "+f"(acc[mt][nt][0]), "+f"(acc[mt][nt][1]),
                                   "+f"(acc[mt][nt][2]), "+f"(acc[mt][nt][3])
                                 : "r"(af[mt][0]), "r"(af[mt][1]), "r"(af[mt][2]), "r"(af[mt][3]),
                                   "r"(bfr[nt][0]), "r"(bfr[nt][1]));
                }
        }
        __syncthreads();   // all reads of this slot done before refill

        // Refill this slot with tile t+STAGES (empty commit keeps group count aligned)
        if (t + STAGES < NT) {
            const int kt = (t + STAGES) * BK;
            #pragma unroll
            for (int i = 0; i < 4; i++) {
                int idx = tid + i * 256;
                int k  = idx >> 5, mc = (idx & 31) << 2;
                cp16(&Af[slot * (BK * BM) + k * BM + mc],
                     gA + (size_t)(kt + k) * HW + p0 + mc);
                int n = idx >> 2, kc = (idx & 3) << 3;
                cp16(&Bs[slot * B_STAGE_H + n * B_ROW_H + kc],
                     &g_Wh[n * CIMG + kt + kc]);
            }
        }
        asm volatile("cp.async.commit_group;");
    }

    // Epilogue: write fp16 channel-last pix
    const int mrow = lane >> 2;
    const int ncol = (lane & 3) * 2;
    #pragma unroll
    for (int mt = 0; mt < 4; mt++) {
        #pragma unroll
        for (int nt = 0; nt < 8; nt++) {
            int m = wm * 64 + mt * 16 + mrow;
            int n = wn * 64 + nt * 8 + ncol;
            size_t base = ((size_t)(b * HW + p0 + m)) * CPT + n;
            *reinterpret_cast<__half2*>(&g_pix[base]) =
                __floats2half2_rn(acc[mt][nt][0], acc[mt][nt][1]);
            *reinterpret_cast<__half2*>(&g_pix[base + 8 * CPT]) =
                __floats2half2_rn(acc[mt][nt][2], acc[mt][nt][3]);
        }
    }
}

// ---------------------------------------------------------------------------
// Kernel 2: per-point projection + bilinear combine of precomputed pix + bias
//   One warp per point, 8 channels per lane (uint4 corner reads, float4 IO).
// ---------------------------------------------------------------------------
__global__ void fuse_kernel(const float* __restrict__ pf,
                            const float* __restrict__ centers,
                            const float* __restrict__ P2,
                            const float* __restrict__ R0,
                            const float* __restrict__ Tr,
                            const float* __restrict__ bias,
                            const int*   __restrict__ bidx,
                            float* __restrict__ out) {
    const int gw   = (blockIdx.x * blockDim.x + threadIdx.x) >> 5;
    const int lane = threadIdx.x & 31;
    if (gw >= NPTS) return;
    const int n = gw;
    const int b = bidx[n];

    const float px = centers[n * 3 + 0];
    const float py = centers[n * 3 + 1];
    const float pz = centers[n * 3 + 2];
    const float* tr = Tr + b * 16;
    const float* r0 = R0 + b * 16;
    const float* p2 = P2 + b * 12;

    float cam[4], rect[4], im[3];
    #pragma unroll
    for (int i = 0; i < 4; i++)
        cam[i] = tr[i*4+0]*px + tr[i*4+1]*py + tr[i*4+2]*pz + tr[i*4+3];
    #pragma unroll
    for (int i = 0; i < 4; i++)
        rect[i] = r0[i*4+0]*cam[0] + r0[i*4+1]*cam[1] + r0[i*4+2]*cam[2] + r0[i*4+3]*cam[3];
    #pragma unroll
    for (int i = 0; i < 3; i++)
        im[i] = p2[i*4+0]*rect[0] + p2[i*4+1]*rect[1] + p2[i*4+2]*rect[2] + p2[i*4+3]*rect[3];

    const float zc    = im[2];
    const float depth = fmaxf(zc, 1e-5f);
    const float u     = im[0] / depth;
    const float v     = im[1] / depth;
    const bool valid  = (zc > 0.f) && (u >= 0.f) && (u < (float)IMW) && (v >= 0.f) && (v < (float)IMH);

    const float x0f = floorf(u), y0f = floorf(v);
    const float wx1 = u - x0f, wx0 = 1.f - wx1;
    const float wy1 = v - y0f, wy0 = 1.f - wy1;
    const int xi0 = (int)x0f, yi0 = (int)y0f;

    const float cw[4] = {wx0 * wy0, wx1 * wy0, wx0 * wy1, wx1 * wy1};
    float wgt[4];
    const __half* rp[4];
    #pragma unroll
    for (int k = 0; k < 4; k++) {
        int xi = xi0 + (k & 1);
        int yi = yi0 + (k >> 1);
        bool inb = (xi >= 0) && (xi <= IMW - 1) && (yi >= 0) && (yi <= IMH - 1);
        wgt[k] = (valid && inb) ? cw[k] : 0.f;
        int xc = min(max(xi, 0), IMW - 1);
        int yc = min(max(yi, 0), IMH - 1);
        rp[k] = &g_pix[((size_t)((b * IMH + yc) * IMW + xc)) * CPT];
    }

    const int c = lane * 8;                 // 8 channels per lane
    float a[8];
    #pragma unroll
    for (int j = 0; j < 8; j++) a[j] = 0.f;

    #pragma unroll
    for (int k = 0; k < 4; k++) {
        if (wgt[k] != 0.f) {
            uint4 raw = *reinterpret_cast<const uint4*>(rp[k] + c);
            const __half2* h = reinterpret_cast<const __half2*>(&raw);
            #pragma unroll
            for (int j = 0; j < 4; j++) {
                float2 f = __half22float2(h[j]);
                a[2*j]   = fmaf(wgt[k], f.x, a[2*j]);
                a[2*j+1] = fmaf(wgt[k], f.y, a[2*j+1]);
            }
        }
    }

    const float* pfrow = pf + (size_t)n * CPT + c;
    float*       orow  = out + (size_t)n * CPT + c;
    #pragma unroll
    for (int h = 0; h < 2; h++) {
        float4 pfv = *reinterpret_cast<const float4*>(pfrow + h * 4);
        float4 bv  = *reinterpret_cast<const float4*>(bias + c + h * 4);
        float4 o;
        o.x = pfv.x + (a[4*h+0] + bv.x);
        o.y = pfv.y + (a[4*h+1] + bv.y);
        o.z = pfv.z + (a[4*h+2] + bv.z);
        o.w = pfv.w + (a[4*h+3] + bv.w);
        *reinterpret_cast<float4*>(orow + h * 4) = o;
    }
}

// ---------------------------------------------------------------------------
// Launch
// ---------------------------------------------------------------------------
extern "C" void kernel_launch(void* const* d_in, const int* in_sizes, int n_in,
                              void* d_out, int out_size) {
    const float* point_feat = (const float*)d_in[0];
    const float* centers    = (const float*)d_in[1];
    const float* img_feat   = (const float*)d_in[2];
    const float* P2         = (const float*)d_in[3];
    const float* R0         = (const float*)d_in[4];
    const float* Tr         = (const float*)d_in[5];
    const float* align_w    = (const float*)d_in[6];
    const float* align_b    = (const float*)d_in[7];
    const int*   bidx       = (const int*)d_in[8];
    float* out = (float*)d_out;

    // Idempotent attribute set (not an allocation; safe under graph capture)
    cudaFuncSetAttribute(gemm_pix_kernel,
                         cudaFuncAttributeMaxDynamicSharedMemorySize, SMEM_TOTAL);

    convW_kernel<<<(CPT * CIMG + 255) / 256, 256>>>(align_w);
    gemm_pix_kernel<<<dim3(HW / BM, 1, BSZ), 256, SMEM_TOTAL>>>(img_feat);
    fuse_kernel<<<(NPTS + 7) / 8, 256>>>(point_feat, centers, P2, R0, Tr, align_b, bidx, out);
}

// round 6
// speedup vs baseline: 1.6131x; 1.1121x over previous
#include <cuda_runtime.h>
#include <cuda_fp16.h>
#include <cstdint>

#define NPTS 100000
#define BSZ  8
#define CIMG 512
#define CPT  256
#define IMH  48
#define IMW  160
#define HW   (IMH*IMW)      /* 7680  */
#define NPIX (BSZ*HW)       /* 61440 */

// Scratch (device globals; no allocation in kernel_launch)
__device__ __half g_Wh[CPT * CIMG];                  // align_w in fp16, row-major (256,512)
__device__ __half g_pix[(size_t)NPIX * CPT];         // channel-last projected pixels, fp16

// ---------------------------------------------------------------------------
// Kernel 0: convert align_w (f32) -> fp16
// ---------------------------------------------------------------------------
__global__ void convW_kernel(const float* __restrict__ W) {
    int i = blockIdx.x * blockDim.x + threadIdx.x;
    if (i < CPT * CIMG) g_Wh[i] = __float2half_rn(W[i]);
}

// ---------------------------------------------------------------------------
// Kernel 1: per-batch GEMM  pix_b(7680x256) = G_b^T(7680x512) @ W^T(512x256)
//   cp.async 3-stage pipeline, BM=64 x BN=256 (M split -> A still read once,
//   B re-read from L2 only). Warp tile 32x64 -> 64 accum regs -> 2 CTAs/SM:
//   convert-hop + syncs of one CTA overlap the other CTA's HMMA issue.
// ---------------------------------------------------------------------------
#define BM 64
#define BN 256
#define BK 32
#define STAGES 3

#define A_STAGE_F     (BK * BM)                /* 2048 f32 = 8192 B  */
#define B_ROW_H       (BK + 8)                 /* 40 halves, 80B row */
#define B_STAGE_H     (BN * B_ROW_H)           /* 10240 halves = 20480 B */
#define AH_ROW_H      (BM + 8)                 /* 72 halves */
#define SMEM_TOTAL (STAGES * A_STAGE_F * 4 + STAGES * B_STAGE_H * 2 + BK * AH_ROW_H * 2)

__device__ __forceinline__ void cp16(void* s, const void* g) {
    uint32_t sa = (uint32_t)__cvta_generic_to_shared(s);
    asm volatile("cp.async.cg.shared.global [%0], [%1], 16;" :: "r"(sa), "l"(g));
}

__global__ __launch_bounds__(256, 2)
void gemm_pix_kernel(const float* __restrict__ img) {
    extern __shared__ char smem_raw[];
    float*  Af = reinterpret_cast<float*>(smem_raw);                           // [STAGES][BK][BM]
    __half* Bs = reinterpret_cast<__half*>(smem_raw + STAGES * A_STAGE_F * 4); // [STAGES][BN][B_ROW_H]
    __half* Ah = reinterpret_cast<__half*>(smem_raw + STAGES * A_STAGE_F * 4
                                           + STAGES * B_STAGE_H * 2);          // [BK][AH_ROW_H]

    const int b  = blockIdx.z;
    const int p0 = blockIdx.x * BM;
    const float* gA = img + (size_t)b * CIMG * HW;

    const int tid  = threadIdx.x;
    const int lane = tid & 31;
    const int warp = tid >> 5;
    const int wm   = warp & 1;    // m offset wm*32
    const int wn   = warp >> 1;   // n offset wn*64

    float acc[2][8][4];
    #pragma unroll
    for (int i = 0; i < 2; i++)
        #pragma unroll
        for (int j = 0; j < 8; j++)
            #pragma unroll
            for (int k = 0; k < 4; k++) acc[i][j][k] = 0.f;

    // Copy mapping per stage:
    //   A: 512 16B chunks -> 2/thread.  k = idx>>4, m-chunk = (idx&15)*4
    //   B: 1024 16B chunks -> 4/thread. n = idx>>2, k-chunk = (idx&3)*8

    // Prologue: issue STAGES tiles
    #pragma unroll
    for (int s = 0; s < STAGES; s++) {
        const int kt = s * BK;
        #pragma unroll
        for (int i = 0; i < 2; i++) {
            int idx = tid + i * 256;
            int k  = idx >> 4, mc = (idx & 15) << 2;
            cp16(&Af[s * A_STAGE_F + k * BM + mc],
                 gA + (size_t)(kt + k) * HW + p0 + mc);
        }
        #pragma unroll
        for (int i = 0; i < 4; i++) {
            int idx = tid + i * 256;
            int n = idx >> 2, kc = (idx & 3) << 3;
            cp16(&Bs[s * B_STAGE_H + n * B_ROW_H + kc],
                 &g_Wh[n * CIMG + kt + kc]);
        }
        asm volatile("cp.async.commit_group;");
    }

    const int NT = CIMG / BK;   // 16
    for (int t = 0; t < NT; t++) {
        asm volatile("cp.async.wait_group %0;" :: "n"(STAGES - 1));
        __syncthreads();
        const int slot = t % STAGES;

        // Convert f32 stage -> fp16 Ah (512 float4, 2/thread)
        #pragma unroll
        for (int i = 0; i < 2; i++) {
            int idx = tid + i * 256;
            int k = idx >> 4, m4 = (idx & 15) << 2;
            float4 v = *reinterpret_cast<const float4*>(&Af[slot * A_STAGE_F + k * BM + m4]);
            *reinterpret_cast<__half2*>(&Ah[k * AH_ROW_H + m4])     = __floats2half2_rn(v.x, v.y);
            *reinterpret_cast<__half2*>(&Ah[k * AH_ROW_H + m4 + 2]) = __floats2half2_rn(v.z, v.w);
        }
        __syncthreads();

        #pragma unroll
        for (int ks = 0; ks < BK; ks += 16) {
            uint32_t af[2][4];
            uint32_t bfr[8][2];
            {
                int jj = lane >> 3, r = lane & 7;
                int m_off = (jj & 1) * 8, k_off = (jj >> 1) * 8;
                #pragma unroll
                for (int mt = 0; mt < 2; mt++) {
                    uint32_t addr = (uint32_t)__cvta_generic_to_shared(
                        &Ah[(ks + k_off + r) * AH_ROW_H + wm * 32 + mt * 16 + m_off]);
                    asm volatile("ldmatrix.sync.aligned.m8n8.x4.trans.shared.b16 {%0,%1,%2,%3}, [%4];"
                                 : "=r"(af[mt][0]), "=r"(af[mt][1]), "=r"(af[mt][2]), "=r"(af[mt][3])
                                 : "r"(addr));
                }
                int jb = (lane >> 3) & 1;
                #pragma unroll
                for (int nt = 0; nt < 8; nt++) {
                    uint32_t addr = (uint32_t)__cvta_generic_to_shared(
                        &Bs[slot * B_STAGE_H + (wn * 64 + nt * 8 + r) * B_ROW_H + ks + jb * 8]);
                    asm volatile("ldmatrix.sync.aligned.m8n8.x2.shared.b16 {%0,%1}, [%2];"
                                 : "=r"(bfr[nt][0]), "=r"(bfr[nt][1])
                                 : "r"(addr));
                }
            }
            #pragma unroll
            for (int mt = 0; mt < 2; mt++)
                #pragma unroll
                for (int nt = 0; nt < 8; nt++) {
                    asm volatile("mma.sync.aligned.m16n8k16.row.col.f32.f16.f16.f32 "
                                 "{%0,%1,%2,%3}, {%4,%5,%6,%7}, {%8,%9}, {%0,%1,%2,%3};"
                                 : "+f"(acc[mt][nt][0]), "+f"(acc[mt][nt][1]),
                                   "+f"(acc[mt][nt][2]), "+f"(acc[mt][nt][3])
                                 : "r"(af[mt][0]), "r"(af[mt][1]), "r"(af[mt][2]), "r"(af[mt][3]),
                                   "r"(bfr[nt][0]), "r"(bfr[nt][1]));
                }
        }
        __syncthreads();   // all reads of this slot done before refill

        // Refill this slot with tile t+STAGES
        if (t + STAGES < NT) {
            const int kt = (t + STAGES) * BK;
            #pragma unroll
            for (int i = 0; i < 2; i++) {
                int idx = tid + i * 256;
                int k  = idx >> 4, mc = (idx & 15) << 2;
                cp16(&Af[slot * A_STAGE_F + k * BM + mc],
                     gA + (size_t)(kt + k) * HW + p0 + mc);
            }
            #pragma unroll
            for (int i = 0; i < 4; i++) {
                int idx = tid + i * 256;
                int n = idx >> 2, kc = (idx & 3) << 3;
                cp16(&Bs[slot * B_STAGE_H + n * B_ROW_H + kc],
                     &g_Wh[n * CIMG + kt + kc]);
            }
        }
        asm volatile("cp.async.commit_group;");
    }

    // Epilogue: write fp16 channel-last pix
    const int mrow = lane >> 2;
    const int ncol = (lane & 3) * 2;
    #pragma unroll
    for (int mt = 0; mt < 2; mt++) {
        #pragma unroll
        for (int nt = 0; nt < 8; nt++) {
            int m = wm * 32 + mt * 16 + mrow;
            int n = wn * 64 + nt * 8 + ncol;
            size_t base = ((size_t)(b * HW + p0 + m)) * CPT + n;
            *reinterpret_cast<__half2*>(&g_pix[base]) =
                __floats2half2_rn(acc[mt][nt][0], acc[mt][nt][1]);
            *reinterpret_cast<__half2*>(&g_pix[base + 8 * CPT]) =
                __floats2half2_rn(acc[mt][nt][2], acc[mt][nt][3]);
        }
    }
}

// ---------------------------------------------------------------------------
// Kernel 2: per-point projection + bilinear combine of precomputed pix + bias
//   One warp per point, 8 channels per lane (uint4 corner reads, float4 IO).
// ---------------------------------------------------------------------------
__global__ void fuse_kernel(const float* __restrict__ pf,
                            const float* __restrict__ centers,
                            const float* __restrict__ P2,
                            const float* __restrict__ R0,
                            const float* __restrict__ Tr,
                            const float* __restrict__ bias,
                            const int*   __restrict__ bidx,
                            float* __restrict__ out) {
    const int gw   = (blockIdx.x * blockDim.x + threadIdx.x) >> 5;
    const int lane = threadIdx.x & 31;
    if (gw >= NPTS) return;
    const int n = gw;
    const int b = bidx[n];

    const float px = centers[n * 3 + 0];
    const float py = centers[n * 3 + 1];
    const float pz = centers[n * 3 + 2];
    const float* tr = Tr + b * 16;
    const float* r0 = R0 + b * 16;
    const float* p2 = P2 + b * 12;

    float cam[4], rect[4], im[3];
    #pragma unroll
    for (int i = 0; i < 4; i++)
        cam[i] = tr[i*4+0]*px + tr[i*4+1]*py + tr[i*4+2]*pz + tr[i*4+3];
    #pragma unroll
    for (int i = 0; i < 4; i++)
        rect[i] = r0[i*4+0]*cam[0] + r0[i*4+1]*cam[1] + r0[i*4+2]*cam[2] + r0[i*4+3]*cam[3];
    #pragma unroll
    for (int i = 0; i < 3; i++)
        im[i] = p2[i*4+0]*rect[0] + p2[i*4+1]*rect[1] + p2[i*4+2]*rect[2] + p2[i*4+3]*rect[3];

    const float zc    = im[2];
    const float depth = fmaxf(zc, 1e-5f);
    const float u     = im[0] / depth;
    const float v     = im[1] / depth;
    const bool valid  = (zc > 0.f) && (u >= 0.f) && (u < (float)IMW) && (v >= 0.f) && (v < (float)IMH);

    const float x0f = floorf(u), y0f = floorf(v);
    const float wx1 = u - x0f, wx0 = 1.f - wx1;
    const float wy1 = v - y0f, wy0 = 1.f - wy1;
    const int xi0 = (int)x0f, yi0 = (int)y0f;

    const float cw[4] = {wx0 * wy0, wx1 * wy0, wx0 * wy1, wx1 * wy1};
    float wgt[4];
    const __half* rp[4];
    #pragma unroll
    for (int k = 0; k < 4; k++) {
        int xi = xi0 + (k & 1);
        int yi = yi0 + (k >> 1);
        bool inb = (xi >= 0) && (xi <= IMW - 1) && (yi >= 0) && (yi <= IMH - 1);
        wgt[k] = (valid && inb) ? cw[k] : 0.f;
        int xc = min(max(xi, 0), IMW - 1);
        int yc = min(max(yi, 0), IMH - 1);
        rp[k] = &g_pix[((size_t)((b * IMH + yc) * IMW + xc)) * CPT];
    }

    const int c = lane * 8;                 // 8 channels per lane
    float a[8];
    #pragma unroll
    for (int j = 0; j < 8; j++) a[j] = 0.f;

    #pragma unroll
    for (int k = 0; k < 4; k++) {
        if (wgt[k] != 0.f) {
            uint4 raw = *reinterpret_cast<const uint4*>(rp[k] + c);
            const __half2* h = reinterpret_cast<const __half2*>(&raw);
            #pragma unroll
            for (int j = 0; j < 4; j++) {
                float2 f = __half22float2(h[j]);
                a[2*j]   = fmaf(wgt[k], f.x, a[2*j]);
                a[2*j+1] = fmaf(wgt[k], f.y, a[2*j+1]);
            }
        }
    }

    const float* pfrow = pf + (size_t)n * CPT + c;
    float*       orow  = out + (size_t)n * CPT + c;
    #pragma unroll
    for (int h = 0; h < 2; h++) {
        float4 pfv = *reinterpret_cast<const float4*>(pfrow + h * 4);
        float4 bv  = *reinterpret_cast<const float4*>(bias + c + h * 4);
        float4 o;
        o.x = pfv.x + (a[4*h+0] + bv.x);
        o.y = pfv.y + (a[4*h+1] + bv.y);
        o.z = pfv.z + (a[4*h+2] + bv.z);
        o.w = pfv.w + (a[4*h+3] + bv.w);
        *reinterpret_cast<float4*>(orow + h * 4) = o;
    }
}

// ---------------------------------------------------------------------------
// Launch
// ---------------------------------------------------------------------------
extern "C" void kernel_launch(void* const* d_in, const int* in_sizes, int n_in,
                              void* d_out, int out_size) {
    const float* point_feat = (const float*)d_in[0];
    const float* centers    = (const float*)d_in[1];
    const float* img_feat   = (const float*)d_in[2];
    const float* P2         = (const float*)d_in[3];
    const float* R0         = (const float*)d_in[4];
    const float* Tr         = (const float*)d_in[5];
    const float* align_w    = (const float*)d_in[6];
    const float* align_b    = (const float*)d_in[7];
    const int*   bidx       = (const int*)d_in[8];
    float* out = (float*)d_out;

    // Idempotent attribute set (not an allocation; safe under graph capture)
    cudaFuncSetAttribute(gemm_pix_kernel,
                         cudaFuncAttributeMaxDynamicSharedMemorySize, SMEM_TOTAL);

    convW_kernel<<<(CPT * CIMG + 255) / 256, 256>>>(align_w);
    gemm_pix_kernel<<<dim3(HW / BM, 1, BSZ), 256, SMEM_TOTAL>>>(img_feat);
    fuse_kernel<<<(NPTS + 7) / 8, 256>>>(point_feat, centers, P2, R0, Tr, align_b, bidx, out);
}